// round 1
// baseline (speedup 1.0000x reference)
#include <cuda_runtime.h>
#include <math.h>

#define B_   2
#define L_   8192
#define D_   1024
#define H_   16
#define DH_  64
#define M_   266
#define MPAD 272
#define BL   (B_*L_)
#define BH   (B_*H_)

#define SCALE  0.17677669529663687f   /* 1024^-0.25 */
#define SCALE2 0.03125f               /* SCALE^2 */
#define NC     0.061313932f           /* 266^-0.5 */
#define KEPS   1e-4f
#define NSTAB  1e-6f

#define SPLIT 32
#define KVSZ  (BH*M_*65)
#define OUT_CHUNKS 4

// ---------------- device scratch (no mallocs allowed) ----------------
__device__ float g_Qp[BL*D_];
__device__ float g_Kp[BL*D_];
__device__ float g_Vp[BL*D_];
__device__ float g_ctx[BL*D_];
__device__ float g_hk[BH*L_];
__device__ unsigned int g_kstab;
__device__ float g_kv[KVSZ];
__device__ float g_kvpart[(size_t)SPLIT*KVSZ];

// ---------------- init ----------------
__global__ void init_kernel() {
    if (threadIdx.x == 0) g_kstab = 0xFF800000u; // -inf bits
}

// ---------------- SGEMM: C[M,1024] = A[M,1024] @ W[1024,1024]^T + bias ----------------
__global__ __launch_bounds__(256) void sgemm_bias(const float* __restrict__ A,
                                                  const float* __restrict__ W,
                                                  const float* __restrict__ bias,
                                                  float* __restrict__ C) {
    const int K = D_, N = D_;
    __shared__ float As[16][128];
    __shared__ float Bs[16][128];
    int tid = threadIdx.x;
    int tx = tid & 15, ty = tid >> 4;
    const float* Ab = A + (size_t)blockIdx.y * 128 * K;
    const float* Wb = W + (size_t)blockIdx.x * 128 * K;
    float acc[8][8];
    #pragma unroll
    for (int i = 0; i < 8; ++i)
        #pragma unroll
        for (int j = 0; j < 8; ++j) acc[i][j] = 0.f;

    for (int k0 = 0; k0 < K; k0 += 16) {
        #pragma unroll
        for (int i = 0; i < 2; ++i) {
            int idx = tid + i * 256;
            int row = idx >> 2;
            int c4  = (idx & 3) << 2;
            float4 va = *(const float4*)(Ab + (size_t)row * K + k0 + c4);
            As[c4+0][row]=va.x; As[c4+1][row]=va.y; As[c4+2][row]=va.z; As[c4+3][row]=va.w;
            float4 vb = *(const float4*)(Wb + (size_t)row * K + k0 + c4);
            Bs[c4+0][row]=vb.x; Bs[c4+1][row]=vb.y; Bs[c4+2][row]=vb.z; Bs[c4+3][row]=vb.w;
        }
        __syncthreads();
        #pragma unroll
        for (int kk = 0; kk < 16; ++kk) {
            float af[8], bf[8];
            *(float4*)&af[0] = *(const float4*)&As[kk][ty*8];
            *(float4*)&af[4] = *(const float4*)&As[kk][ty*8+4];
            *(float4*)&bf[0] = *(const float4*)&Bs[kk][tx*8];
            *(float4*)&bf[4] = *(const float4*)&Bs[kk][tx*8+4];
            #pragma unroll
            for (int i = 0; i < 8; ++i)
                #pragma unroll
                for (int j = 0; j < 8; ++j)
                    acc[i][j] = fmaf(af[i], bf[j], acc[i][j]);
        }
        __syncthreads();
    }
    int rb = blockIdx.y * 128 + ty * 8;
    int cb = blockIdx.x * 128 + tx * 8;
    #pragma unroll
    for (int i = 0; i < 8; ++i) {
        #pragma unroll
        for (int j = 0; j < 8; j += 4) {
            float4 o;
            o.x = acc[i][j]   + bias[cb+j];
            o.y = acc[i][j+1] + bias[cb+j+1];
            o.z = acc[i][j+2] + bias[cb+j+2];
            o.w = acc[i][j+3] + bias[cb+j+3];
            *(float4*)(C + (size_t)(rb+i) * N + cb + j) = o;
        }
    }
}

// ---------------- h_k per (b,h,l) + global max into g_kstab ----------------
__global__ __launch_bounds__(256) void hk_kernel() {
    int gid = blockIdx.x * 256 + threadIdx.x;   // over BH*L_
    int b = gid / (H_ * L_);
    int rem = gid % (H_ * L_);
    int h = rem / L_;
    int l = rem % L_;
    const float4* row = (const float4*)(g_Kp + (size_t)(b * L_ + l) * D_ + h * DH_);
    float s = 0.f;
    #pragma unroll
    for (int t = 0; t < 16; ++t) {
        float4 v = row[t];
        s = fmaf(v.x, v.x, s); s = fmaf(v.y, v.y, s);
        s = fmaf(v.z, v.z, s); s = fmaf(v.w, v.w, s);
    }
    float hk = -0.5f * SCALE2 * s;   // <= 0 always
    g_hk[gid] = hk;
    float m = hk;
    #pragma unroll
    for (int o = 16; o > 0; o >>= 1) m = fmaxf(m, __shfl_xor_sync(0xffffffffu, m, o));
    __shared__ float wmax[8];
    if ((threadIdx.x & 31) == 0) wmax[threadIdx.x >> 5] = m;
    __syncthreads();
    if (threadIdx.x == 0) {
        float bm = wmax[0];
        #pragma unroll
        for (int w = 1; w < 8; ++w) bm = fmaxf(bm, wmax[w]);
        // for non-positive floats, min over uint bits == max over floats
        atomicMin(&g_kstab, __float_as_uint(bm));
    }
}

// proj micro-tile: 2 rows (l0,l1) x 4 features (m0..m0+3), K=64 via float4
__device__ __forceinline__ void proj4x2(const float* __restrict__ sIn,
                                        const float* __restrict__ sWf,
                                        int l0, int l1, int m0, float p[2][4]) {
    const float4* a0 = (const float4*)(sIn + l0 * 68);
    const float4* a1 = (const float4*)(sIn + l1 * 68);
    #pragma unroll
    for (int t = 0; t < 16; ++t) {
        float4 va0 = a0[t], va1 = a1[t];
        #pragma unroll
        for (int j = 0; j < 4; ++j) {
            float4 w = *(const float4*)(sWf + (m0 + j) * 68 + t * 4);
            p[0][j] = fmaf(va0.x, w.x, p[0][j]);
            p[0][j] = fmaf(va0.y, w.y, p[0][j]);
            p[0][j] = fmaf(va0.z, w.z, p[0][j]);
            p[0][j] = fmaf(va0.w, w.w, p[0][j]);
            p[1][j] = fmaf(va1.x, w.x, p[1][j]);
            p[1][j] = fmaf(va1.y, w.y, p[1][j]);
            p[1][j] = fmaf(va1.z, w.z, p[1][j]);
            p[1][j] = fmaf(va1.w, w.w, p[1][j]);
        }
    }
}

// ---------------- kv kernel: partial kv_aug[m, 0..64] per (split,b,h) ----------------
#define KV_SMEM_FLOATS (266*68 + 32*68 + 32*80 + 32*MPAD + 32 + 32)
__global__ __launch_bounds__(256, 1) void kv_kernel(const float* __restrict__ Wf,
                                                    const float* __restrict__ mask) {
    extern __shared__ float sm[];
    float* sWf    = sm;                    // [266][68]
    float* sK     = sWf + 266*68;          // [32][68]
    float* sV     = sK + 32*68;            // [32][80]
    float* kprime = sV + 32*80;            // [32][272]
    float* shk    = kprime + 32*MPAD;      // [32]
    float* smask  = shk + 32;              // [32]

    int tid = threadIdx.x;
    int split = blockIdx.x;
    int h = blockIdx.y, b = blockIdx.z;
    int bh = b * H_ + h;

    for (int idx = tid; idx < M_ * DH_; idx += 256)
        sWf[(idx >> 6) * 68 + (idx & 63)] = Wf[idx];

    float kstab = __uint_as_float(g_kstab);

    const int lt = tid & 15;
    const int mt = tid >> 4;
    const int tx = tid & 15;
    const int ty = tid >> 4;

    float acc[17][5];
    #pragma unroll
    for (int i = 0; i < 17; ++i)
        #pragma unroll
        for (int j = 0; j < 5; ++j) acc[i][j] = 0.f;

    int lstart = split * (L_ / SPLIT);   // 256 rows per block
    for (int c = 0; c < (L_ / SPLIT) / 32; ++c) {
        int lbase = lstart + c * 32;
        __syncthreads();   // protect smem from previous chunk's phase2
        for (int idx = tid; idx < 32 * 16; idx += 256) {
            int i = idx >> 4, t = idx & 15;
            float4 v = *(const float4*)(g_Kp + (size_t)(b * L_ + lbase + i) * D_ + h * DH_ + t * 4);
            v.x *= SCALE; v.y *= SCALE; v.z *= SCALE; v.w *= SCALE;
            *(float4*)(sK + i * 68 + t * 4) = v;
        }
        for (int idx = tid; idx < 32 * 20; idx += 256) {
            int i = idx / 20, t = idx % 20;
            float4 v;
            if (t < 16) v = *(const float4*)(g_Vp + (size_t)(b * L_ + lbase + i) * D_ + h * DH_ + t * 4);
            else if (t == 16) v = make_float4(1.f, 0.f, 0.f, 0.f);
            else v = make_float4(0.f, 0.f, 0.f, 0.f);
            *(float4*)(sV + i * 80 + t * 4) = v;
        }
        if (tid < 32) {
            shk[tid]   = g_hk[(size_t)bh * L_ + lbase + tid];
            smask[tid] = mask[(size_t)b * L_ + lbase + tid];
        }
        __syncthreads();
        // phase 1: k' rows for this chunk
        #pragma unroll
        for (int q = 0; q < 5; ++q) {
            int mq = mt + 16 * q;
            if (mq < 68) {
                int m0 = mq << 2;
                float p[2][4] = {{0,0,0,0},{0,0,0,0}};
                proj4x2(sK, sWf, lt, lt + 16, m0, p);
                float hs0 = shk[lt] - kstab,    hs1 = shk[lt+16] - kstab;
                float mk0 = smask[lt],          mk1 = smask[lt+16];
                float4 o0, o1;
                o0.x = (m0+0 < M_) ? NC*(__expf(p[0][0]+hs0)+KEPS)*mk0 : 0.f;
                o0.y = (m0+1 < M_) ? NC*(__expf(p[0][1]+hs0)+KEPS)*mk0 : 0.f;
                o0.z = (m0+2 < M_) ? NC*(__expf(p[0][2]+hs0)+KEPS)*mk0 : 0.f;
                o0.w = (m0+3 < M_) ? NC*(__expf(p[0][3]+hs0)+KEPS)*mk0 : 0.f;
                o1.x = (m0+0 < M_) ? NC*(__expf(p[1][0]+hs1)+KEPS)*mk1 : 0.f;
                o1.y = (m0+1 < M_) ? NC*(__expf(p[1][1]+hs1)+KEPS)*mk1 : 0.f;
                o1.z = (m0+2 < M_) ? NC*(__expf(p[1][2]+hs1)+KEPS)*mk1 : 0.f;
                o1.w = (m0+3 < M_) ? NC*(__expf(p[1][3]+hs1)+KEPS)*mk1 : 0.f;
                *(float4*)(kprime + lt * MPAD + m0)        = o0;
                *(float4*)(kprime + (lt + 16) * MPAD + m0) = o1;
            }
        }
        __syncthreads();
        // phase 2: acc[m,d] += k'[l,m] * v_aug[l,d]
        #pragma unroll 4
        for (int l = 0; l < 32; ++l) {
            float kp[17], vv[5];
            #pragma unroll
            for (int i = 0; i < 17; ++i) kp[i] = kprime[l * MPAD + ty + 16 * i];
            #pragma unroll
            for (int j = 0; j < 5; ++j) vv[j] = sV[l * 80 + tx + 16 * j];
            #pragma unroll
            for (int i = 0; i < 17; ++i)
                #pragma unroll
                for (int j = 0; j < 5; ++j)
                    acc[i][j] = fmaf(kp[i], vv[j], acc[i][j]);
        }
    }
    size_t base = ((size_t)split * BH + bh) * (M_ * 65);
    #pragma unroll
    for (int i = 0; i < 17; ++i) {
        int m = ty + 16 * i;
        if (m < M_) {
            #pragma unroll
            for (int j = 0; j < 5; ++j) {
                int d = tx + 16 * j;
                if (d < 65) g_kvpart[base + m * 65 + d] = acc[i][j];
            }
        }
    }
}

// ---------------- deterministic reduce of kv partials ----------------
__global__ void kv_reduce() {
    int idx = blockIdx.x * 256 + threadIdx.x;
    if (idx < KVSZ) {
        float s = 0.f;
        #pragma unroll
        for (int p = 0; p < SPLIT; ++p) s += g_kvpart[(size_t)p * KVSZ + idx];
        g_kv[idx] = s;
    }
}

// ---------------- out kernel: ctx = (q' @ kv_aug) / denom, head-merged ----------------
#define OUT_SMEM_FLOATS (266*68 + 32*68 + 32*MPAD + 266*68 + 256 + 32)
__global__ __launch_bounds__(256, 1) void out_kernel(const float* __restrict__ Wf) {
    extern __shared__ float sm[];
    float* sWf    = sm;                    // [266][68]
    float* sQ     = sWf + 266*68;          // [32][68]
    float* qprime = sQ + 32*68;            // [32][272]
    float* skv    = qprime + 32*MPAD;      // [266][68]
    float* sdenp  = skv + 266*68;          // [256]
    float* sden   = sdenp + 256;           // [32]

    int tid = threadIdx.x;
    int h = blockIdx.y, b = blockIdx.z;
    int bh = b * H_ + h;

    for (int idx = tid; idx < M_ * DH_; idx += 256)
        sWf[(idx >> 6) * 68 + (idx & 63)] = Wf[idx];
    const float* kvp = g_kv + (size_t)bh * (M_ * 65);
    for (int idx = tid; idx < M_ * 68; idx += 256) {
        int m = idx / 68, d = idx % 68;
        skv[idx] = (d < 65) ? kvp[m * 65 + d] : 0.f;
    }

    const int lt = tid & 15;
    const int mt = tid >> 4;
    const int tx = tid & 15;
    const int ty = tid >> 4;

    for (int c = 0; c < OUT_CHUNKS; ++c) {
        int lbase = (blockIdx.x * OUT_CHUNKS + c) * 32;
        __syncthreads();
        for (int idx = tid; idx < 32 * 16; idx += 256) {
            int i = idx >> 4, t = idx & 15;
            float4 v = *(const float4*)(g_Qp + (size_t)(b * L_ + lbase + i) * D_ + h * DH_ + t * 4);
            v.x *= SCALE; v.y *= SCALE; v.z *= SCALE; v.w *= SCALE;
            *(float4*)(sQ + i * 68 + t * 4) = v;
        }
        __syncthreads();
        // phase 1: q' = NC*(exp(proj_q)+eps)
        #pragma unroll
        for (int q = 0; q < 5; ++q) {
            int mq = mt + 16 * q;
            if (mq < 68) {
                int m0 = mq << 2;
                float p[2][4] = {{0,0,0,0},{0,0,0,0}};
                proj4x2(sQ, sWf, lt, lt + 16, m0, p);
                float4 o0, o1;
                o0.x = (m0+0 < M_) ? NC*(__expf(p[0][0])+KEPS) : 0.f;
                o0.y = (m0+1 < M_) ? NC*(__expf(p[0][1])+KEPS) : 0.f;
                o0.z = (m0+2 < M_) ? NC*(__expf(p[0][2])+KEPS) : 0.f;
                o0.w = (m0+3 < M_) ? NC*(__expf(p[0][3])+KEPS) : 0.f;
                o1.x = (m0+0 < M_) ? NC*(__expf(p[1][0])+KEPS) : 0.f;
                o1.y = (m0+1 < M_) ? NC*(__expf(p[1][1])+KEPS) : 0.f;
                o1.z = (m0+2 < M_) ? NC*(__expf(p[1][2])+KEPS) : 0.f;
                o1.w = (m0+3 < M_) ? NC*(__expf(p[1][3])+KEPS) : 0.f;
                *(float4*)(qprime + lt * MPAD + m0)        = o0;
                *(float4*)(qprime + (lt + 16) * MPAD + m0) = o1;
            }
        }
        __syncthreads();
        // denominator: d_l = sum_m q'[l,m] * ksum[m]  (ksum = kv column 64)
        {
            int slice = tid & 7;
            int l = tid >> 3;
            float p = 0.f;
            for (int m = slice; m < M_; m += 8)
                p = fmaf(qprime[l * MPAD + m], skv[m * 68 + 64], p);
            sdenp[tid] = p;
        }
        __syncthreads();
        if (tid < 32) {
            float d = 0.f;
            #pragma unroll
            for (int s = 0; s < 8; ++s) d += sdenp[tid * 8 + s];
            if (fabsf(d) <= NSTAB) d += 2.f * NSTAB;
            sden[tid] = 1.0f / d;
        }
        __syncthreads();
        // phase 2: out[l, 0..63] = q'[l,:] @ kv[:, 0..63]
        int l0 = 2 * ty, l1 = 2 * ty + 1;
        float4 a0 = make_float4(0,0,0,0), a1 = make_float4(0,0,0,0);
        #pragma unroll 2
        for (int m = 0; m < M_; ++m) {
            float q0 = qprime[l0 * MPAD + m];
            float q1 = qprime[l1 * MPAD + m];
            float4 kvv = *(const float4*)(skv + m * 68 + tx * 4);
            a0.x = fmaf(q0, kvv.x, a0.x); a0.y = fmaf(q0, kvv.y, a0.y);
            a0.z = fmaf(q0, kvv.z, a0.z); a0.w = fmaf(q0, kvv.w, a0.w);
            a1.x = fmaf(q1, kvv.x, a1.x); a1.y = fmaf(q1, kvv.y, a1.y);
            a1.z = fmaf(q1, kvv.z, a1.z); a1.w = fmaf(q1, kvv.w, a1.w);
        }
        float i0 = sden[l0], i1 = sden[l1];
        a0.x *= i0; a0.y *= i0; a0.z *= i0; a0.w *= i0;
        a1.x *= i1; a1.y *= i1; a1.z *= i1; a1.w *= i1;
        *(float4*)(g_ctx + (size_t)(b * L_ + lbase + l0) * D_ + h * DH_ + tx * 4) = a0;
        *(float4*)(g_ctx + (size_t)(b * L_ + lbase + l1) * D_ + h * DH_ + tx * 4) = a1;
    }
}

// ---------------- launch ----------------
extern "C" void kernel_launch(void* const* d_in, const int* in_sizes, int n_in,
                              void* d_out, int out_size) {
    const float* query = (const float*)d_in[0];
    const float* key   = (const float*)d_in[1];
    const float* value = (const float*)d_in[2];
    const float* mask  = (const float*)d_in[3];
    const float* Wq = (const float*)d_in[4];
    const float* bq = (const float*)d_in[5];
    const float* Wk = (const float*)d_in[6];
    const float* bk = (const float*)d_in[7];
    const float* Wv = (const float*)d_in[8];
    const float* bv = (const float*)d_in[9];
    const float* Wo = (const float*)d_in[10];
    const float* bo = (const float*)d_in[11];
    const float* Wf = (const float*)d_in[12];

    float *Qp, *Kp, *Vp, *ctx;
    cudaGetSymbolAddress((void**)&Qp,  g_Qp);
    cudaGetSymbolAddress((void**)&Kp,  g_Kp);
    cudaGetSymbolAddress((void**)&Vp,  g_Vp);
    cudaGetSymbolAddress((void**)&ctx, g_ctx);

    cudaFuncSetAttribute(kv_kernel,  cudaFuncAttributeMaxDynamicSharedMemorySize,
                         KV_SMEM_FLOATS * (int)sizeof(float));
    cudaFuncSetAttribute(out_kernel, cudaFuncAttributeMaxDynamicSharedMemorySize,
                         OUT_SMEM_FLOATS * (int)sizeof(float));

    init_kernel<<<1, 32>>>();

    dim3 gg(D_ / 128, BL / 128);
    sgemm_bias<<<gg, 256>>>(query, Wq, bq, Qp);
    sgemm_bias<<<gg, 256>>>(key,   Wk, bk, Kp);
    sgemm_bias<<<gg, 256>>>(value, Wv, bv, Vp);

    hk_kernel<<<(BH * L_) / 256, 256>>>();

    kv_kernel<<<dim3(SPLIT, H_, B_), 256, KV_SMEM_FLOATS * sizeof(float)>>>(Wf, mask);
    kv_reduce<<<(KVSZ + 255) / 256, 256>>>();

    out_kernel<<<dim3(L_ / (32 * OUT_CHUNKS), H_, B_), 256,
                 OUT_SMEM_FLOATS * sizeof(float)>>>(Wf);

    sgemm_bias<<<gg, 256>>>(ctx, Wo, bo, (float*)d_out);
}

// round 3
// speedup vs baseline: 1.6641x; 1.6641x over previous
#include <cuda_runtime.h>
#include <cstdint>
#include <math.h>

#define B_   2
#define L_   8192
#define D_   1024
#define H_   16
#define DH_  64
#define M_   266
#define MPAD 272
#define BL   (B_*L_)
#define BH   (B_*H_)

#define SCALE  0.17677669529663687f   /* 1024^-0.25 */
#define SCALE2 0.03125f               /* SCALE^2 */
#define NC     0.061313932f           /* 266^-0.5 */
#define KEPS   1e-4f
#define NSTAB  1e-6f

#define SPLIT 32
#define KVSZ  (BH*M_*65)
#define OUT_CHUNKS 4

// ---------------- device scratch (no mallocs allowed) ----------------
__device__ float g_Qp[BL*D_];
__device__ float g_Kp[BL*D_];
__device__ float g_Vp[BL*D_];
__device__ float g_ctx[BL*D_];
__device__ float g_hk[BH*L_];
__device__ unsigned int g_kstab;
__device__ float g_kv[KVSZ];
__device__ float g_kvpart[(size_t)SPLIT*KVSZ];

// ================= helpers =================
__device__ __forceinline__ uint32_t smem_u32(const void* p) {
    uint32_t a;
    asm("{ .reg .u64 t; cvta.to.shared.u64 t, %1; cvt.u32.u64 %0, t; }" : "=r"(a) : "l"(p));
    return a;
}

// split fp32x4 -> bf16x4 hi + bf16x4 lo (packed as 2x u32 each)
__device__ __forceinline__ void cvt_split(float4 v, uint32_t& h01, uint32_t& h23,
                                          uint32_t& l01, uint32_t& l23) {
    asm("cvt.rn.bf16x2.f32 %0, %1, %2;" : "=r"(h01) : "f"(v.y), "f"(v.x));
    asm("cvt.rn.bf16x2.f32 %0, %1, %2;" : "=r"(h23) : "f"(v.w), "f"(v.z));
    float r0 = v.x - __uint_as_float(h01 << 16);
    float r1 = v.y - __uint_as_float(h01 & 0xffff0000u);
    float r2 = v.z - __uint_as_float(h23 << 16);
    float r3 = v.w - __uint_as_float(h23 & 0xffff0000u);
    asm("cvt.rn.bf16x2.f32 %0, %1, %2;" : "=r"(l01) : "f"(r1), "f"(r0));
    asm("cvt.rn.bf16x2.f32 %0, %1, %2;" : "=r"(l23) : "f"(r3), "f"(r2));
}

#define LDSM_X4(r0, r1, r2, r3, addr)                                        \
    asm volatile("ldmatrix.sync.aligned.m8n8.x4.shared.b16 {%0,%1,%2,%3}, [%4];" \
        : "=r"(r0), "=r"(r1), "=r"(r2), "=r"(r3) : "r"(addr))

#define MMA_BF16(d, a, b0_, b1_)                                             \
    asm volatile("mma.sync.aligned.m16n8k16.row.col.f32.bf16.bf16.f32 "      \
        "{%0,%1,%2,%3}, {%4,%5,%6,%7}, {%8,%9}, {%0,%1,%2,%3};"              \
        : "+f"((d)[0]), "+f"((d)[1]), "+f"((d)[2]), "+f"((d)[3])             \
        : "r"((a)[0]), "r"((a)[1]), "r"((a)[2]), "r"((a)[3]),                \
          "r"(b0_), "r"(b1_))

// ================= bf16x3 mma.sync GEMM: C[16384,1024] = A @ W^T + bias =================
// CTA tile 128x128, K-chunk 32, 8 warps (2x4), warp tile 64x32.
#define AST 40   /* padded smem row stride in bf16 elements (80B) */

__global__ __launch_bounds__(256, 2) void gemm_mma(const float* __restrict__ A,
                                                   const float* __restrict__ W,
                                                   const float* __restrict__ bias,
                                                   float* __restrict__ C) {
    __shared__ uint16_t sAh[128 * AST];
    __shared__ uint16_t sAl[128 * AST];
    __shared__ uint16_t sBh[128 * AST];
    __shared__ uint16_t sBl[128 * AST];

    const int tid  = threadIdx.x;
    const int lane = tid & 31;
    const int wid  = tid >> 5;
    const int wm   = wid & 1;    // 0..1 -> 64-row slice
    const int wn   = wid >> 1;   // 0..3 -> 32-col slice

    const size_t mbase = (size_t)blockIdx.y * 128;
    const size_t nbase = (size_t)blockIdx.x * 128;
    const float* Ab = A + mbase * D_;
    const float* Wb = W + nbase * D_;

    const uint32_t aH = smem_u32(sAh), aL = smem_u32(sAl);
    const uint32_t bH = smem_u32(sBh), bL = smem_u32(sBl);

    // ldmatrix per-lane addressing pieces
    const int arow    = lane & 15;
    const int acolsel = (lane >> 4) << 3;               // 0 or 8
    const int brow    = (lane & 7) + ((lane >> 4) << 3); // 0..15
    const int bcolsel = ((lane >> 3) & 1) << 3;          // 0 or 8

    float acc[4][4][4];
    #pragma unroll
    for (int i = 0; i < 4; ++i)
        #pragma unroll
        for (int j = 0; j < 4; ++j)
            #pragma unroll
            for (int k = 0; k < 4; ++k) acc[i][j][k] = 0.f;

    for (int kc = 0; kc < D_ / 32; ++kc) {
        __syncthreads();
        // fill smem: 128 rows x 8 float4 per matrix; 4 float4 per thread each
        #pragma unroll
        for (int j = 0; j < 4; ++j) {
            int fidx = tid + j * 256;     // 0..1023
            int r = fidx >> 3;
            int u = fidx & 7;
            float4 v = *(const float4*)(Ab + (size_t)r * D_ + kc * 32 + u * 4);
            uint32_t h01, h23, l01, l23;
            cvt_split(v, h01, h23, l01, l23);
            *(uint2*)(sAh + r * AST + u * 4) = make_uint2(h01, h23);
            *(uint2*)(sAl + r * AST + u * 4) = make_uint2(l01, l23);
            float4 w = *(const float4*)(Wb + (size_t)r * D_ + kc * 32 + u * 4);
            cvt_split(w, h01, h23, l01, l23);
            *(uint2*)(sBh + r * AST + u * 4) = make_uint2(h01, h23);
            *(uint2*)(sBl + r * AST + u * 4) = make_uint2(l01, l23);
        }
        __syncthreads();

        #pragma unroll
        for (int ks = 0; ks < 2; ++ks) {
            uint32_t af[4][4], bhF[2][4], blF[2][4];
            #pragma unroll
            for (int mt = 0; mt < 4; ++mt) {
                uint32_t off = (uint32_t)(((wm * 64 + mt * 16 + arow) * AST
                                          + ks * 16 + acolsel) * 2);
                LDSM_X4(af[mt][0], af[mt][1], af[mt][2], af[mt][3], aH + off);
            }
            #pragma unroll
            for (int bp = 0; bp < 2; ++bp) {
                uint32_t off = (uint32_t)(((wn * 32 + bp * 16 + brow) * AST
                                          + ks * 16 + bcolsel) * 2);
                LDSM_X4(bhF[bp][0], bhF[bp][1], bhF[bp][2], bhF[bp][3], bH + off);
                LDSM_X4(blF[bp][0], blF[bp][1], blF[bp][2], blF[bp][3], bL + off);
            }
            // pass 1: hi x hi, pass 2: hi x lo
            #pragma unroll
            for (int mt = 0; mt < 4; ++mt) {
                #pragma unroll
                for (int nt = 0; nt < 4; ++nt) {
                    uint32_t b0 = bhF[nt >> 1][(nt & 1) * 2];
                    uint32_t b1 = bhF[nt >> 1][(nt & 1) * 2 + 1];
                    MMA_BF16(acc[mt][nt], af[mt], b0, b1);
                    uint32_t c0 = blF[nt >> 1][(nt & 1) * 2];
                    uint32_t c1 = blF[nt >> 1][(nt & 1) * 2 + 1];
                    MMA_BF16(acc[mt][nt], af[mt], c0, c1);
                }
            }
            // pass 3: lo x hi (reload A frags from lo tile)
            #pragma unroll
            for (int mt = 0; mt < 4; ++mt) {
                uint32_t off = (uint32_t)(((wm * 64 + mt * 16 + arow) * AST
                                          + ks * 16 + acolsel) * 2);
                LDSM_X4(af[mt][0], af[mt][1], af[mt][2], af[mt][3], aL + off);
            }
            #pragma unroll
            for (int mt = 0; mt < 4; ++mt) {
                #pragma unroll
                for (int nt = 0; nt < 4; ++nt) {
                    uint32_t b0 = bhF[nt >> 1][(nt & 1) * 2];
                    uint32_t b1 = bhF[nt >> 1][(nt & 1) * 2 + 1];
                    MMA_BF16(acc[mt][nt], af[mt], b0, b1);
                }
            }
        }
    }

    // epilogue: direct fp32 stores + bias
    #pragma unroll
    for (int mt = 0; mt < 4; ++mt) {
        size_t r0 = mbase + wm * 64 + mt * 16 + (lane >> 2);
        #pragma unroll
        for (int nt = 0; nt < 4; ++nt) {
            int col = (int)nbase + wn * 32 + nt * 8 + 2 * (lane & 3);
            float bx = bias[col], by = bias[col + 1];
            float2 v0 = make_float2(acc[mt][nt][0] + bx, acc[mt][nt][1] + by);
            float2 v1 = make_float2(acc[mt][nt][2] + bx, acc[mt][nt][3] + by);
            *(float2*)(C + r0 * D_ + col)       = v0;
            *(float2*)(C + (r0 + 8) * D_ + col) = v1;
        }
    }
}

// ---------------- init ----------------
__global__ void init_kernel() {
    if (threadIdx.x == 0) g_kstab = 0xFF800000u; // -inf bits
}

// ---------------- h_k per (b,h,l) + global max into g_kstab ----------------
__global__ __launch_bounds__(256) void hk_kernel() {
    int gid = blockIdx.x * 256 + threadIdx.x;   // over BH*L_
    int b = gid / (H_ * L_);
    int rem = gid % (H_ * L_);
    int h = rem / L_;
    int l = rem % L_;
    const float4* row = (const float4*)(g_Kp + (size_t)(b * L_ + l) * D_ + h * DH_);
    float s = 0.f;
    #pragma unroll
    for (int t = 0; t < 16; ++t) {
        float4 v = row[t];
        s = fmaf(v.x, v.x, s); s = fmaf(v.y, v.y, s);
        s = fmaf(v.z, v.z, s); s = fmaf(v.w, v.w, s);
    }
    float hk = -0.5f * SCALE2 * s;   // <= 0 always
    g_hk[gid] = hk;
    float m = hk;
    #pragma unroll
    for (int o = 16; o > 0; o >>= 1) m = fmaxf(m, __shfl_xor_sync(0xffffffffu, m, o));
    __shared__ float wmax[8];
    if ((threadIdx.x & 31) == 0) wmax[threadIdx.x >> 5] = m;
    __syncthreads();
    if (threadIdx.x == 0) {
        float bm = wmax[0];
        #pragma unroll
        for (int w = 1; w < 8; ++w) bm = fmaxf(bm, wmax[w]);
        atomicMin(&g_kstab, __float_as_uint(bm));
    }
}

// proj micro-tile: 2 rows (l0,l1) x 4 features (m0..m0+3), K=64 via float4
__device__ __forceinline__ void proj4x2(const float* __restrict__ sIn,
                                        const float* __restrict__ sWf,
                                        int l0, int l1, int m0, float p[2][4]) {
    const float4* a0 = (const float4*)(sIn + l0 * 68);
    const float4* a1 = (const float4*)(sIn + l1 * 68);
    #pragma unroll
    for (int t = 0; t < 16; ++t) {
        float4 va0 = a0[t], va1 = a1[t];
        #pragma unroll
        for (int j = 0; j < 4; ++j) {
            float4 w = *(const float4*)(sWf + (m0 + j) * 68 + t * 4);
            p[0][j] = fmaf(va0.x, w.x, p[0][j]);
            p[0][j] = fmaf(va0.y, w.y, p[0][j]);
            p[0][j] = fmaf(va0.z, w.z, p[0][j]);
            p[0][j] = fmaf(va0.w, w.w, p[0][j]);
            p[1][j] = fmaf(va1.x, w.x, p[1][j]);
            p[1][j] = fmaf(va1.y, w.y, p[1][j]);
            p[1][j] = fmaf(va1.z, w.z, p[1][j]);
            p[1][j] = fmaf(va1.w, w.w, p[1][j]);
        }
    }
}

// ---------------- kv kernel: partial kv_aug[m, 0..64] per (split,b,h) ----------------
#define KV_SMEM_FLOATS (266*68 + 32*68 + 32*80 + 32*MPAD + 32 + 32)
__global__ __launch_bounds__(256, 1) void kv_kernel(const float* __restrict__ Wf,
                                                    const float* __restrict__ mask) {
    extern __shared__ float sm[];
    float* sWf    = sm;                    // [266][68]
    float* sK     = sWf + 266*68;          // [32][68]
    float* sV     = sK + 32*68;            // [32][80]
    float* kprime = sV + 32*80;            // [32][272]
    float* shk    = kprime + 32*MPAD;      // [32]
    float* smask  = shk + 32;              // [32]

    int tid = threadIdx.x;
    int split = blockIdx.x;
    int h = blockIdx.y, b = blockIdx.z;
    int bh = b * H_ + h;

    for (int idx = tid; idx < M_ * DH_; idx += 256)
        sWf[(idx >> 6) * 68 + (idx & 63)] = Wf[idx];

    float kstab = __uint_as_float(g_kstab);

    const int lt = tid & 15;
    const int mt = tid >> 4;
    const int tx = tid & 15;
    const int ty = tid >> 4;

    float acc[17][5];
    #pragma unroll
    for (int i = 0; i < 17; ++i)
        #pragma unroll
        for (int j = 0; j < 5; ++j) acc[i][j] = 0.f;

    int lstart = split * (L_ / SPLIT);   // 256 rows per block
    for (int c = 0; c < (L_ / SPLIT) / 32; ++c) {
        int lbase = lstart + c * 32;
        __syncthreads();
        for (int idx = tid; idx < 32 * 16; idx += 256) {
            int i = idx >> 4, t = idx & 15;
            float4 v = *(const float4*)(g_Kp + (size_t)(b * L_ + lbase + i) * D_ + h * DH_ + t * 4);
            v.x *= SCALE; v.y *= SCALE; v.z *= SCALE; v.w *= SCALE;
            *(float4*)(sK + i * 68 + t * 4) = v;
        }
        for (int idx = tid; idx < 32 * 20; idx += 256) {
            int i = idx / 20, t = idx % 20;
            float4 v;
            if (t < 16) v = *(const float4*)(g_Vp + (size_t)(b * L_ + lbase + i) * D_ + h * DH_ + t * 4);
            else if (t == 16) v = make_float4(1.f, 0.f, 0.f, 0.f);
            else v = make_float4(0.f, 0.f, 0.f, 0.f);
            *(float4*)(sV + i * 80 + t * 4) = v;
        }
        if (tid < 32) {
            shk[tid]   = g_hk[(size_t)bh * L_ + lbase + tid];
            smask[tid] = mask[(size_t)b * L_ + lbase + tid];
        }
        __syncthreads();
        #pragma unroll
        for (int q = 0; q < 5; ++q) {
            int mq = mt + 16 * q;
            if (mq < 68) {
                int m0 = mq << 2;
                float p[2][4] = {{0,0,0,0},{0,0,0,0}};
                proj4x2(sK, sWf, lt, lt + 16, m0, p);
                float hs0 = shk[lt] - kstab,    hs1 = shk[lt+16] - kstab;
                float mk0 = smask[lt],          mk1 = smask[lt+16];
                float4 o0, o1;
                o0.x = (m0+0 < M_) ? NC*(__expf(p[0][0]+hs0)+KEPS)*mk0 : 0.f;
                o0.y = (m0+1 < M_) ? NC*(__expf(p[0][1]+hs0)+KEPS)*mk0 : 0.f;
                o0.z = (m0+2 < M_) ? NC*(__expf(p[0][2]+hs0)+KEPS)*mk0 : 0.f;
                o0.w = (m0+3 < M_) ? NC*(__expf(p[0][3]+hs0)+KEPS)*mk0 : 0.f;
                o1.x = (m0+0 < M_) ? NC*(__expf(p[1][0]+hs1)+KEPS)*mk1 : 0.f;
                o1.y = (m0+1 < M_) ? NC*(__expf(p[1][1]+hs1)+KEPS)*mk1 : 0.f;
                o1.z = (m0+2 < M_) ? NC*(__expf(p[1][2]+hs1)+KEPS)*mk1 : 0.f;
                o1.w = (m0+3 < M_) ? NC*(__expf(p[1][3]+hs1)+KEPS)*mk1 : 0.f;
                *(float4*)(kprime + lt * MPAD + m0)        = o0;
                *(float4*)(kprime + (lt + 16) * MPAD + m0) = o1;
            }
        }
        __syncthreads();
        #pragma unroll 4
        for (int l = 0; l < 32; ++l) {
            float kp[17], vv[5];
            #pragma unroll
            for (int i = 0; i < 17; ++i) kp[i] = kprime[l * MPAD + ty + 16 * i];
            #pragma unroll
            for (int j = 0; j < 5; ++j) vv[j] = sV[l * 80 + tx + 16 * j];
            #pragma unroll
            for (int i = 0; i < 17; ++i)
                #pragma unroll
                for (int j = 0; j < 5; ++j)
                    acc[i][j] = fmaf(kp[i], vv[j], acc[i][j]);
        }
    }
    size_t base = ((size_t)split * BH + bh) * (M_ * 65);
    #pragma unroll
    for (int i = 0; i < 17; ++i) {
        int m = ty + 16 * i;
        if (m < M_) {
            #pragma unroll
            for (int j = 0; j < 5; ++j) {
                int d = tx + 16 * j;
                if (d < 65) g_kvpart[base + m * 65 + d] = acc[i][j];
            }
        }
    }
}

// ---------------- deterministic reduce of kv partials ----------------
__global__ void kv_reduce() {
    int idx = blockIdx.x * 256 + threadIdx.x;
    if (idx < KVSZ) {
        float s = 0.f;
        #pragma unroll
        for (int p = 0; p < SPLIT; ++p) s += g_kvpart[(size_t)p * KVSZ + idx];
        g_kv[idx] = s;
    }
}

// ---------------- out kernel: ctx = (q' @ kv_aug) / denom, head-merged ----------------
#define OUT_SMEM_FLOATS (266*68 + 32*68 + 32*MPAD + 266*68 + 256 + 32)
__global__ __launch_bounds__(256, 1) void out_kernel(const float* __restrict__ Wf) {
    extern __shared__ float sm[];
    float* sWf    = sm;                    // [266][68]
    float* sQ     = sWf + 266*68;          // [32][68]
    float* qprime = sQ + 32*68;            // [32][272]
    float* skv    = qprime + 32*MPAD;      // [266][68]
    float* sdenp  = skv + 266*68;          // [256]
    float* sden   = sdenp + 256;           // [32]

    int tid = threadIdx.x;
    int h = blockIdx.y, b = blockIdx.z;
    int bh = b * H_ + h;

    for (int idx = tid; idx < M_ * DH_; idx += 256)
        sWf[(idx >> 6) * 68 + (idx & 63)] = Wf[idx];
    const float* kvp = g_kv + (size_t)bh * (M_ * 65);
    for (int idx = tid; idx < M_ * 68; idx += 256) {
        int m = idx / 68, d = idx % 68;
        skv[idx] = (d < 65) ? kvp[m * 65 + d] : 0.f;
    }

    const int lt = tid & 15;
    const int mt = tid >> 4;
    const int tx = tid & 15;
    const int ty = tid >> 4;

    for (int c = 0; c < OUT_CHUNKS; ++c) {
        int lbase = (blockIdx.x * OUT_CHUNKS + c) * 32;
        __syncthreads();
        for (int idx = tid; idx < 32 * 16; idx += 256) {
            int i = idx >> 4, t = idx & 15;
            float4 v = *(const float4*)(g_Qp + (size_t)(b * L_ + lbase + i) * D_ + h * DH_ + t * 4);
            v.x *= SCALE; v.y *= SCALE; v.z *= SCALE; v.w *= SCALE;
            *(float4*)(sQ + i * 68 + t * 4) = v;
        }
        __syncthreads();
        #pragma unroll
        for (int q = 0; q < 5; ++q) {
            int mq = mt + 16 * q;
            if (mq < 68) {
                int m0 = mq << 2;
                float p[2][4] = {{0,0,0,0},{0,0,0,0}};
                proj4x2(sQ, sWf, lt, lt + 16, m0, p);
                float4 o0, o1;
                o0.x = (m0+0 < M_) ? NC*(__expf(p[0][0])+KEPS) : 0.f;
                o0.y = (m0+1 < M_) ? NC*(__expf(p[0][1])+KEPS) : 0.f;
                o0.z = (m0+2 < M_) ? NC*(__expf(p[0][2])+KEPS) : 0.f;
                o0.w = (m0+3 < M_) ? NC*(__expf(p[0][3])+KEPS) : 0.f;
                o1.x = (m0+0 < M_) ? NC*(__expf(p[1][0])+KEPS) : 0.f;
                o1.y = (m0+1 < M_) ? NC*(__expf(p[1][1])+KEPS) : 0.f;
                o1.z = (m0+2 < M_) ? NC*(__expf(p[1][2])+KEPS) : 0.f;
                o1.w = (m0+3 < M_) ? NC*(__expf(p[1][3])+KEPS) : 0.f;
                *(float4*)(qprime + lt * MPAD + m0)        = o0;
                *(float4*)(qprime + (lt + 16) * MPAD + m0) = o1;
            }
        }
        __syncthreads();
        {
            int slice = tid & 7;
            int l = tid >> 3;
            float p = 0.f;
            for (int m = slice; m < M_; m += 8)
                p = fmaf(qprime[l * MPAD + m], skv[m * 68 + 64], p);
            sdenp[tid] = p;
        }
        __syncthreads();
        if (tid < 32) {
            float d = 0.f;
            #pragma unroll
            for (int s = 0; s < 8; ++s) d += sdenp[tid * 8 + s];
            if (fabsf(d) <= NSTAB) d += 2.f * NSTAB;
            sden[tid] = 1.0f / d;
        }
        __syncthreads();
        int l0 = 2 * ty, l1 = 2 * ty + 1;
        float4 a0 = make_float4(0,0,0,0), a1 = make_float4(0,0,0,0);
        #pragma unroll 2
        for (int m = 0; m < M_; ++m) {
            float q0 = qprime[l0 * MPAD + m];
            float q1 = qprime[l1 * MPAD + m];
            float4 kvv = *(const float4*)(skv + m * 68 + tx * 4);
            a0.x = fmaf(q0, kvv.x, a0.x); a0.y = fmaf(q0, kvv.y, a0.y);
            a0.z = fmaf(q0, kvv.z, a0.z); a0.w = fmaf(q0, kvv.w, a0.w);
            a1.x = fmaf(q1, kvv.x, a1.x); a1.y = fmaf(q1, kvv.y, a1.y);
            a1.z = fmaf(q1, kvv.z, a1.z); a1.w = fmaf(q1, kvv.w, a1.w);
        }
        float i0 = sden[l0], i1 = sden[l1];
        a0.x *= i0; a0.y *= i0; a0.z *= i0; a0.w *= i0;
        a1.x *= i1; a1.y *= i1; a1.z *= i1; a1.w *= i1;
        *(float4*)(g_ctx + (size_t)(b * L_ + lbase + l0) * D_ + h * DH_ + tx * 4) = a0;
        *(float4*)(g_ctx + (size_t)(b * L_ + lbase + l1) * D_ + h * DH_ + tx * 4) = a1;
    }
}

// ---------------- launch ----------------
extern "C" void kernel_launch(void* const* d_in, const int* in_sizes, int n_in,
                              void* d_out, int out_size) {
    const float* query = (const float*)d_in[0];
    const float* key   = (const float*)d_in[1];
    const float* value = (const float*)d_in[2];
    const float* mask  = (const float*)d_in[3];
    const float* Wq = (const float*)d_in[4];
    const float* bq = (const float*)d_in[5];
    const float* Wk = (const float*)d_in[6];
    const float* bk = (const float*)d_in[7];
    const float* Wv = (const float*)d_in[8];
    const float* bv = (const float*)d_in[9];
    const float* Wo = (const float*)d_in[10];
    const float* bo = (const float*)d_in[11];
    const float* Wf = (const float*)d_in[12];

    float *Qp, *Kp, *Vp, *ctx;
    cudaGetSymbolAddress((void**)&Qp,  g_Qp);
    cudaGetSymbolAddress((void**)&Kp,  g_Kp);
    cudaGetSymbolAddress((void**)&Vp,  g_Vp);
    cudaGetSymbolAddress((void**)&ctx, g_ctx);

    cudaFuncSetAttribute(kv_kernel,  cudaFuncAttributeMaxDynamicSharedMemorySize,
                         KV_SMEM_FLOATS * (int)sizeof(float));
    cudaFuncSetAttribute(out_kernel, cudaFuncAttributeMaxDynamicSharedMemorySize,
                         OUT_SMEM_FLOATS * (int)sizeof(float));

    init_kernel<<<1, 32>>>();

    dim3 gg(D_ / 128, BL / 128);
    gemm_mma<<<gg, 256>>>(query, Wq, bq, Qp);
    gemm_mma<<<gg, 256>>>(key,   Wk, bk, Kp);
    gemm_mma<<<gg, 256>>>(value, Wv, bv, Vp);

    hk_kernel<<<(BH * L_) / 256, 256>>>();

    kv_kernel<<<dim3(SPLIT, H_, B_), 256, KV_SMEM_FLOATS * sizeof(float)>>>(Wf, mask);
    kv_reduce<<<(KVSZ + 255) / 256, 256>>>();

    out_kernel<<<dim3(L_ / (32 * OUT_CHUNKS), H_, B_), 256,
                 OUT_SMEM_FLOATS * sizeof(float)>>>(Wf);

    gemm_mma<<<gg, 256>>>(ctx, Wo, bo, (float*)d_out);
}

// round 4
// speedup vs baseline: 1.6659x; 1.0010x over previous
#include <cuda_runtime.h>
#include <cstdint>
#include <math.h>

#define B_   2
#define L_   8192
#define D_   1024
#define H_   16
#define DH_  64
#define M_   266
#define MPAD 272
#define BL   (B_*L_)
#define BH   (B_*H_)

#define SCALE  0.17677669529663687f   /* 1024^-0.25 */
#define SCALE2 0.03125f               /* SCALE^2 */
#define NC     0.061313932f           /* 266^-0.5 */
#define KEPS   1e-4f
#define NSTAB  1e-6f

#define SPLIT 32
#define KVSZ  (BH*M_*65)
#define OUT_CHUNKS 4

// ---------------- device scratch (no mallocs allowed) ----------------
__device__ float g_Qp[BL*D_];
__device__ float g_Kp[BL*D_];
__device__ float g_Vp[BL*D_];
__device__ float g_ctx[BL*D_];
__device__ float g_hk[BH*L_];
__device__ unsigned int g_kstab;
__device__ float g_kv[KVSZ];
__device__ float g_kvpart[(size_t)SPLIT*KVSZ];

// ================= helpers =================
__device__ __forceinline__ uint32_t smem_u32(const void* p) {
    uint32_t a;
    asm("{ .reg .u64 t; cvta.to.shared.u64 t, %1; cvt.u32.u64 %0, t; }" : "=r"(a) : "l"(p));
    return a;
}

// split fp32x4 -> bf16x4 hi + bf16x4 lo (packed as 2x u32 each)
__device__ __forceinline__ void cvt_split(float4 v, uint32_t& h01, uint32_t& h23,
                                          uint32_t& l01, uint32_t& l23) {
    asm("cvt.rn.bf16x2.f32 %0, %1, %2;" : "=r"(h01) : "f"(v.y), "f"(v.x));
    asm("cvt.rn.bf16x2.f32 %0, %1, %2;" : "=r"(h23) : "f"(v.w), "f"(v.z));
    float r0 = v.x - __uint_as_float(h01 << 16);
    float r1 = v.y - __uint_as_float(h01 & 0xffff0000u);
    float r2 = v.z - __uint_as_float(h23 << 16);
    float r3 = v.w - __uint_as_float(h23 & 0xffff0000u);
    asm("cvt.rn.bf16x2.f32 %0, %1, %2;" : "=r"(l01) : "f"(r1), "f"(r0));
    asm("cvt.rn.bf16x2.f32 %0, %1, %2;" : "=r"(l23) : "f"(r3), "f"(r2));
}

#define LDSM_X4(r0, r1, r2, r3, addr)                                        \
    asm volatile("ldmatrix.sync.aligned.m8n8.x4.shared.b16 {%0,%1,%2,%3}, [%4];" \
        : "=r"(r0), "=r"(r1), "=r"(r2), "=r"(r3) : "r"(addr))

#define MMA_BF16(d, a, b0_, b1_)                                             \
    asm volatile("mma.sync.aligned.m16n8k16.row.col.f32.bf16.bf16.f32 "      \
        "{%0,%1,%2,%3}, {%4,%5,%6,%7}, {%8,%9}, {%0,%1,%2,%3};"              \
        : "+f"((d)[0]), "+f"((d)[1]), "+f"((d)[2]), "+f"((d)[3])             \
        : "r"((a)[0]), "r"((a)[1]), "r"((a)[2]), "r"((a)[3]),                \
          "r"(b0_), "r"(b1_))

// ================= bf16x3 mma.sync GEMM: C[16384,1024] = A @ W^T + bias =================
// CTA tile 128x128, K-chunk 32, 8 warps (2x4), warp tile 64x32.
#define AST 40   /* padded smem row stride in bf16 elements (80B) */

__global__ __launch_bounds__(256, 2) void gemm_mma(const float* __restrict__ A,
                                                   const float* __restrict__ W,
                                                   const float* __restrict__ bias,
                                                   float* __restrict__ C) {
    __shared__ uint16_t sAh[128 * AST];
    __shared__ uint16_t sAl[128 * AST];
    __shared__ uint16_t sBh[128 * AST];
    __shared__ uint16_t sBl[128 * AST];

    const int tid  = threadIdx.x;
    const int lane = tid & 31;
    const int wid  = tid >> 5;
    const int wm   = wid & 1;    // 0..1 -> 64-row slice
    const int wn   = wid >> 1;   // 0..3 -> 32-col slice

    const size_t mbase = (size_t)blockIdx.y * 128;
    const size_t nbase = (size_t)blockIdx.x * 128;
    const float* Ab = A + mbase * D_;
    const float* Wb = W + nbase * D_;

    const uint32_t aH = smem_u32(sAh), aL = smem_u32(sAl);
    const uint32_t bH = smem_u32(sBh), bL = smem_u32(sBl);

    // ldmatrix per-lane addressing pieces
    const int arow    = lane & 15;
    const int acolsel = (lane >> 4) << 3;               // 0 or 8
    const int brow    = (lane & 7) + ((lane >> 4) << 3); // 0..15
    const int bcolsel = ((lane >> 3) & 1) << 3;          // 0 or 8

    float acc[4][4][4];
    #pragma unroll
    for (int i = 0; i < 4; ++i)
        #pragma unroll
        for (int j = 0; j < 4; ++j)
            #pragma unroll
            for (int k = 0; k < 4; ++k) acc[i][j][k] = 0.f;

    for (int kc = 0; kc < D_ / 32; ++kc) {
        __syncthreads();
        // fill smem: 128 rows x 8 float4 per matrix; 4 float4 per thread each
        #pragma unroll
        for (int j = 0; j < 4; ++j) {
            int fidx = tid + j * 256;     // 0..1023
            int r = fidx >> 3;
            int u = fidx & 7;
            float4 v = *(const float4*)(Ab + (size_t)r * D_ + kc * 32 + u * 4);
            uint32_t h01, h23, l01, l23;
            cvt_split(v, h01, h23, l01, l23);
            *(uint2*)(sAh + r * AST + u * 4) = make_uint2(h01, h23);
            *(uint2*)(sAl + r * AST + u * 4) = make_uint2(l01, l23);
            float4 w = *(const float4*)(Wb + (size_t)r * D_ + kc * 32 + u * 4);
            cvt_split(w, h01, h23, l01, l23);
            *(uint2*)(sBh + r * AST + u * 4) = make_uint2(h01, h23);
            *(uint2*)(sBl + r * AST + u * 4) = make_uint2(l01, l23);
        }
        __syncthreads();

        #pragma unroll
        for (int ks = 0; ks < 2; ++ks) {
            uint32_t af[4][4], bhF[2][4], blF[2][4];
            #pragma unroll
            for (int mt = 0; mt < 4; ++mt) {
                uint32_t off = (uint32_t)(((wm * 64 + mt * 16 + arow) * AST
                                          + ks * 16 + acolsel) * 2);
                LDSM_X4(af[mt][0], af[mt][1], af[mt][2], af[mt][3], aH + off);
            }
            #pragma unroll
            for (int bp = 0; bp < 2; ++bp) {
                uint32_t off = (uint32_t)(((wn * 32 + bp * 16 + brow) * AST
                                          + ks * 16 + bcolsel) * 2);
                LDSM_X4(bhF[bp][0], bhF[bp][1], bhF[bp][2], bhF[bp][3], bH + off);
                LDSM_X4(blF[bp][0], blF[bp][1], blF[bp][2], blF[bp][3], bL + off);
            }
            // pass 1: hi x hi, pass 2: hi x lo
            #pragma unroll
            for (int mt = 0; mt < 4; ++mt) {
                #pragma unroll
                for (int nt = 0; nt < 4; ++nt) {
                    uint32_t b0 = bhF[nt >> 1][(nt & 1) * 2];
                    uint32_t b1 = bhF[nt >> 1][(nt & 1) * 2 + 1];
                    MMA_BF16(acc[mt][nt], af[mt], b0, b1);
                    uint32_t c0 = blF[nt >> 1][(nt & 1) * 2];
                    uint32_t c1 = blF[nt >> 1][(nt & 1) * 2 + 1];
                    MMA_BF16(acc[mt][nt], af[mt], c0, c1);
                }
            }
            // pass 3: lo x hi (reload A frags from lo tile)
            #pragma unroll
            for (int mt = 0; mt < 4; ++mt) {
                uint32_t off = (uint32_t)(((wm * 64 + mt * 16 + arow) * AST
                                          + ks * 16 + acolsel) * 2);
                LDSM_X4(af[mt][0], af[mt][1], af[mt][2], af[mt][3], aL + off);
            }
            #pragma unroll
            for (int mt = 0; mt < 4; ++mt) {
                #pragma unroll
                for (int nt = 0; nt < 4; ++nt) {
                    uint32_t b0 = bhF[nt >> 1][(nt & 1) * 2];
                    uint32_t b1 = bhF[nt >> 1][(nt & 1) * 2 + 1];
                    MMA_BF16(acc[mt][nt], af[mt], b0, b1);
                }
            }
        }
    }

    // epilogue: direct fp32 stores + bias
    #pragma unroll
    for (int mt = 0; mt < 4; ++mt) {
        size_t r0 = mbase + wm * 64 + mt * 16 + (lane >> 2);
        #pragma unroll
        for (int nt = 0; nt < 4; ++nt) {
            int col = (int)nbase + wn * 32 + nt * 8 + 2 * (lane & 3);
            float bx = bias[col], by = bias[col + 1];
            float2 v0 = make_float2(acc[mt][nt][0] + bx, acc[mt][nt][1] + by);
            float2 v1 = make_float2(acc[mt][nt][2] + bx, acc[mt][nt][3] + by);
            *(float2*)(C + r0 * D_ + col)       = v0;
            *(float2*)(C + (r0 + 8) * D_ + col) = v1;
        }
    }
}

// ---------------- init ----------------
__global__ void init_kernel() {
    if (threadIdx.x == 0) g_kstab = 0xFF800000u; // -inf bits
}

// ---------------- h_k per (b,h,l) + global max into g_kstab ----------------
__global__ __launch_bounds__(256) void hk_kernel() {
    int gid = blockIdx.x * 256 + threadIdx.x;   // over BH*L_
    int b = gid / (H_ * L_);
    int rem = gid % (H_ * L_);
    int h = rem / L_;
    int l = rem % L_;
    const float4* row = (const float4*)(g_Kp + (size_t)(b * L_ + l) * D_ + h * DH_);
    float s = 0.f;
    #pragma unroll
    for (int t = 0; t < 16; ++t) {
        float4 v = row[t];
        s = fmaf(v.x, v.x, s); s = fmaf(v.y, v.y, s);
        s = fmaf(v.z, v.z, s); s = fmaf(v.w, v.w, s);
    }
    float hk = -0.5f * SCALE2 * s;   // <= 0 always
    g_hk[gid] = hk;
    float m = hk;
    #pragma unroll
    for (int o = 16; o > 0; o >>= 1) m = fmaxf(m, __shfl_xor_sync(0xffffffffu, m, o));
    __shared__ float wmax[8];
    if ((threadIdx.x & 31) == 0) wmax[threadIdx.x >> 5] = m;
    __syncthreads();
    if (threadIdx.x == 0) {
        float bm = wmax[0];
        #pragma unroll
        for (int w = 1; w < 8; ++w) bm = fmaxf(bm, wmax[w]);
        atomicMin(&g_kstab, __float_as_uint(bm));
    }
}

// proj micro-tile: 2 rows (l0,l1) x 4 features (m0..m0+3), K=64 via float4
__device__ __forceinline__ void proj4x2(const float* __restrict__ sIn,
                                        const float* __restrict__ sWf,
                                        int l0, int l1, int m0, float p[2][4]) {
    const float4* a0 = (const float4*)(sIn + l0 * 68);
    const float4* a1 = (const float4*)(sIn + l1 * 68);
    #pragma unroll
    for (int t = 0; t < 16; ++t) {
        float4 va0 = a0[t], va1 = a1[t];
        #pragma unroll
        for (int j = 0; j < 4; ++j) {
            float4 w = *(const float4*)(sWf + (m0 + j) * 68 + t * 4);
            p[0][j] = fmaf(va0.x, w.x, p[0][j]);
            p[0][j] = fmaf(va0.y, w.y, p[0][j]);
            p[0][j] = fmaf(va0.z, w.z, p[0][j]);
            p[0][j] = fmaf(va0.w, w.w, p[0][j]);
            p[1][j] = fmaf(va1.x, w.x, p[1][j]);
            p[1][j] = fmaf(va1.y, w.y, p[1][j]);
            p[1][j] = fmaf(va1.z, w.z, p[1][j]);
            p[1][j] = fmaf(va1.w, w.w, p[1][j]);
        }
    }
}

// ---------------- kv kernel: partial kv_aug[m, 0..64] per (split,b,h) ----------------
#define KV_SMEM_FLOATS (266*68 + 32*68 + 32*80 + 32*MPAD + 32 + 32)
__global__ __launch_bounds__(256, 1) void kv_kernel(const float* __restrict__ Wf,
                                                    const float* __restrict__ mask) {
    extern __shared__ float sm[];
    float* sWf    = sm;                    // [266][68]
    float* sK     = sWf + 266*68;          // [32][68]
    float* sV     = sK + 32*68;            // [32][80]
    float* kprime = sV + 32*80;            // [32][272]
    float* shk    = kprime + 32*MPAD;      // [32]
    float* smask  = shk + 32;              // [32]

    int tid = threadIdx.x;
    int split = blockIdx.x;
    int h = blockIdx.y, b = blockIdx.z;
    int bh = b * H_ + h;

    for (int idx = tid; idx < M_ * DH_; idx += 256)
        sWf[(idx >> 6) * 68 + (idx & 63)] = Wf[idx];

    float kstab = __uint_as_float(g_kstab);

    const int lt = tid & 15;
    const int mt = tid >> 4;
    const int tx = tid & 15;
    const int ty = tid >> 4;

    float acc[17][5];
    #pragma unroll
    for (int i = 0; i < 17; ++i)
        #pragma unroll
        for (int j = 0; j < 5; ++j) acc[i][j] = 0.f;

    int lstart = split * (L_ / SPLIT);   // 256 rows per block
    for (int c = 0; c < (L_ / SPLIT) / 32; ++c) {
        int lbase = lstart + c * 32;
        __syncthreads();
        for (int idx = tid; idx < 32 * 16; idx += 256) {
            int i = idx >> 4, t = idx & 15;
            float4 v = *(const float4*)(g_Kp + (size_t)(b * L_ + lbase + i) * D_ + h * DH_ + t * 4);
            v.x *= SCALE; v.y *= SCALE; v.z *= SCALE; v.w *= SCALE;
            *(float4*)(sK + i * 68 + t * 4) = v;
        }
        for (int idx = tid; idx < 32 * 20; idx += 256) {
            int i = idx / 20, t = idx % 20;
            float4 v;
            if (t < 16) v = *(const float4*)(g_Vp + (size_t)(b * L_ + lbase + i) * D_ + h * DH_ + t * 4);
            else if (t == 16) v = make_float4(1.f, 0.f, 0.f, 0.f);
            else v = make_float4(0.f, 0.f, 0.f, 0.f);
            *(float4*)(sV + i * 80 + t * 4) = v;
        }
        if (tid < 32) {
            shk[tid]   = g_hk[(size_t)bh * L_ + lbase + tid];
            smask[tid] = mask[(size_t)b * L_ + lbase + tid];
        }
        __syncthreads();
        #pragma unroll
        for (int q = 0; q < 5; ++q) {
            int mq = mt + 16 * q;
            if (mq < 68) {
                int m0 = mq << 2;
                float p[2][4] = {{0,0,0,0},{0,0,0,0}};
                proj4x2(sK, sWf, lt, lt + 16, m0, p);
                float hs0 = shk[lt] - kstab,    hs1 = shk[lt+16] - kstab;
                float mk0 = smask[lt],          mk1 = smask[lt+16];
                float4 o0, o1;
                o0.x = (m0+0 < M_) ? NC*(__expf(p[0][0]+hs0)+KEPS)*mk0 : 0.f;
                o0.y = (m0+1 < M_) ? NC*(__expf(p[0][1]+hs0)+KEPS)*mk0 : 0.f;
                o0.z = (m0+2 < M_) ? NC*(__expf(p[0][2]+hs0)+KEPS)*mk0 : 0.f;
                o0.w = (m0+3 < M_) ? NC*(__expf(p[0][3]+hs0)+KEPS)*mk0 : 0.f;
                o1.x = (m0+0 < M_) ? NC*(__expf(p[1][0]+hs1)+KEPS)*mk1 : 0.f;
                o1.y = (m0+1 < M_) ? NC*(__expf(p[1][1]+hs1)+KEPS)*mk1 : 0.f;
                o1.z = (m0+2 < M_) ? NC*(__expf(p[1][2]+hs1)+KEPS)*mk1 : 0.f;
                o1.w = (m0+3 < M_) ? NC*(__expf(p[1][3]+hs1)+KEPS)*mk1 : 0.f;
                *(float4*)(kprime + lt * MPAD + m0)        = o0;
                *(float4*)(kprime + (lt + 16) * MPAD + m0) = o1;
            }
        }
        __syncthreads();
        #pragma unroll 4
        for (int l = 0; l < 32; ++l) {
            float kp[17], vv[5];
            #pragma unroll
            for (int i = 0; i < 17; ++i) kp[i] = kprime[l * MPAD + ty + 16 * i];
            #pragma unroll
            for (int j = 0; j < 5; ++j) vv[j] = sV[l * 80 + tx + 16 * j];
            #pragma unroll
            for (int i = 0; i < 17; ++i)
                #pragma unroll
                for (int j = 0; j < 5; ++j)
                    acc[i][j] = fmaf(kp[i], vv[j], acc[i][j]);
        }
    }
    size_t base = ((size_t)split * BH + bh) * (M_ * 65);
    #pragma unroll
    for (int i = 0; i < 17; ++i) {
        int m = ty + 16 * i;
        if (m < M_) {
            #pragma unroll
            for (int j = 0; j < 5; ++j) {
                int d = tx + 16 * j;
                if (d < 65) g_kvpart[base + m * 65 + d] = acc[i][j];
            }
        }
    }
}

// ---------------- deterministic reduce of kv partials ----------------
__global__ void kv_reduce() {
    int idx = blockIdx.x * 256 + threadIdx.x;
    if (idx < KVSZ) {
        float s = 0.f;
        #pragma unroll
        for (int p = 0; p < SPLIT; ++p) s += g_kvpart[(size_t)p * KVSZ + idx];
        g_kv[idx] = s;
    }
}

// ---------------- out kernel: ctx = (q' @ kv_aug) / denom, head-merged ----------------
#define OUT_SMEM_FLOATS (266*68 + 32*68 + 32*MPAD + 266*68 + 256 + 32)
__global__ __launch_bounds__(256, 1) void out_kernel(const float* __restrict__ Wf) {
    extern __shared__ float sm[];
    float* sWf    = sm;                    // [266][68]
    float* sQ     = sWf + 266*68;          // [32][68]
    float* qprime = sQ + 32*68;            // [32][272]
    float* skv    = qprime + 32*MPAD;      // [266][68]
    float* sdenp  = skv + 266*68;          // [256]
    float* sden   = sdenp + 256;           // [32]

    int tid = threadIdx.x;
    int h = blockIdx.y, b = blockIdx.z;
    int bh = b * H_ + h;

    for (int idx = tid; idx < M_ * DH_; idx += 256)
        sWf[(idx >> 6) * 68 + (idx & 63)] = Wf[idx];
    const float* kvp = g_kv + (size_t)bh * (M_ * 65);
    for (int idx = tid; idx < M_ * 68; idx += 256) {
        int m = idx / 68, d = idx % 68;
        skv[idx] = (d < 65) ? kvp[m * 65 + d] : 0.f;
    }

    const int lt = tid & 15;
    const int mt = tid >> 4;
    const int tx = tid & 15;
    const int ty = tid >> 4;

    for (int c = 0; c < OUT_CHUNKS; ++c) {
        int lbase = (blockIdx.x * OUT_CHUNKS + c) * 32;
        __syncthreads();
        for (int idx = tid; idx < 32 * 16; idx += 256) {
            int i = idx >> 4, t = idx & 15;
            float4 v = *(const float4*)(g_Qp + (size_t)(b * L_ + lbase + i) * D_ + h * DH_ + t * 4);
            v.x *= SCALE; v.y *= SCALE; v.z *= SCALE; v.w *= SCALE;
            *(float4*)(sQ + i * 68 + t * 4) = v;
        }
        __syncthreads();
        #pragma unroll
        for (int q = 0; q < 5; ++q) {
            int mq = mt + 16 * q;
            if (mq < 68) {
                int m0 = mq << 2;
                float p[2][4] = {{0,0,0,0},{0,0,0,0}};
                proj4x2(sQ, sWf, lt, lt + 16, m0, p);
                float4 o0, o1;
                o0.x = (m0+0 < M_) ? NC*(__expf(p[0][0])+KEPS) : 0.f;
                o0.y = (m0+1 < M_) ? NC*(__expf(p[0][1])+KEPS) : 0.f;
                o0.z = (m0+2 < M_) ? NC*(__expf(p[0][2])+KEPS) : 0.f;
                o0.w = (m0+3 < M_) ? NC*(__expf(p[0][3])+KEPS) : 0.f;
                o1.x = (m0+0 < M_) ? NC*(__expf(p[1][0])+KEPS) : 0.f;
                o1.y = (m0+1 < M_) ? NC*(__expf(p[1][1])+KEPS) : 0.f;
                o1.z = (m0+2 < M_) ? NC*(__expf(p[1][2])+KEPS) : 0.f;
                o1.w = (m0+3 < M_) ? NC*(__expf(p[1][3])+KEPS) : 0.f;
                *(float4*)(qprime + lt * MPAD + m0)        = o0;
                *(float4*)(qprime + (lt + 16) * MPAD + m0) = o1;
            }
        }
        __syncthreads();
        {
            int slice = tid & 7;
            int l = tid >> 3;
            float p = 0.f;
            for (int m = slice; m < M_; m += 8)
                p = fmaf(qprime[l * MPAD + m], skv[m * 68 + 64], p);
            sdenp[tid] = p;
        }
        __syncthreads();
        if (tid < 32) {
            float d = 0.f;
            #pragma unroll
            for (int s = 0; s < 8; ++s) d += sdenp[tid * 8 + s];
            if (fabsf(d) <= NSTAB) d += 2.f * NSTAB;
            sden[tid] = 1.0f / d;
        }
        __syncthreads();
        int l0 = 2 * ty, l1 = 2 * ty + 1;
        float4 a0 = make_float4(0,0,0,0), a1 = make_float4(0,0,0,0);
        #pragma unroll 2
        for (int m = 0; m < M_; ++m) {
            float q0 = qprime[l0 * MPAD + m];
            float q1 = qprime[l1 * MPAD + m];
            float4 kvv = *(const float4*)(skv + m * 68 + tx * 4);
            a0.x = fmaf(q0, kvv.x, a0.x); a0.y = fmaf(q0, kvv.y, a0.y);
            a0.z = fmaf(q0, kvv.z, a0.z); a0.w = fmaf(q0, kvv.w, a0.w);
            a1.x = fmaf(q1, kvv.x, a1.x); a1.y = fmaf(q1, kvv.y, a1.y);
            a1.z = fmaf(q1, kvv.z, a1.z); a1.w = fmaf(q1, kvv.w, a1.w);
        }
        float i0 = sden[l0], i1 = sden[l1];
        a0.x *= i0; a0.y *= i0; a0.z *= i0; a0.w *= i0;
        a1.x *= i1; a1.y *= i1; a1.z *= i1; a1.w *= i1;
        *(float4*)(g_ctx + (size_t)(b * L_ + lbase + l0) * D_ + h * DH_ + tx * 4) = a0;
        *(float4*)(g_ctx + (size_t)(b * L_ + lbase + l1) * D_ + h * DH_ + tx * 4) = a1;
    }
}

// ---------------- launch ----------------
extern "C" void kernel_launch(void* const* d_in, const int* in_sizes, int n_in,
                              void* d_out, int out_size) {
    const float* query = (const float*)d_in[0];
    const float* key   = (const float*)d_in[1];
    const float* value = (const float*)d_in[2];
    const float* mask  = (const float*)d_in[3];
    const float* Wq = (const float*)d_in[4];
    const float* bq = (const float*)d_in[5];
    const float* Wk = (const float*)d_in[6];
    const float* bk = (const float*)d_in[7];
    const float* Wv = (const float*)d_in[8];
    const float* bv = (const float*)d_in[9];
    const float* Wo = (const float*)d_in[10];
    const float* bo = (const float*)d_in[11];
    const float* Wf = (const float*)d_in[12];

    float *Qp, *Kp, *Vp, *ctx;
    cudaGetSymbolAddress((void**)&Qp,  g_Qp);
    cudaGetSymbolAddress((void**)&Kp,  g_Kp);
    cudaGetSymbolAddress((void**)&Vp,  g_Vp);
    cudaGetSymbolAddress((void**)&ctx, g_ctx);

    cudaFuncSetAttribute(kv_kernel,  cudaFuncAttributeMaxDynamicSharedMemorySize,
                         KV_SMEM_FLOATS * (int)sizeof(float));
    cudaFuncSetAttribute(out_kernel, cudaFuncAttributeMaxDynamicSharedMemorySize,
                         OUT_SMEM_FLOATS * (int)sizeof(float));

    init_kernel<<<1, 32>>>();

    dim3 gg(D_ / 128, BL / 128);
    gemm_mma<<<gg, 256>>>(query, Wq, bq, Qp);
    gemm_mma<<<gg, 256>>>(key,   Wk, bk, Kp);
    gemm_mma<<<gg, 256>>>(value, Wv, bv, Vp);

    hk_kernel<<<(BH * L_) / 256, 256>>>();

    kv_kernel<<<dim3(SPLIT, H_, B_), 256, KV_SMEM_FLOATS * sizeof(float)>>>(Wf, mask);
    kv_reduce<<<(KVSZ + 255) / 256, 256>>>();

    out_kernel<<<dim3(L_ / (32 * OUT_CHUNKS), H_, B_), 256,
                 OUT_SMEM_FLOATS * sizeof(float)>>>(Wf);

    gemm_mma<<<gg, 256>>>(ctx, Wo, bo, (float*)d_out);
}